// round 1
// baseline (speedup 1.0000x reference)
#include <cuda_runtime.h>
#include <math.h>

#define NLVL 16
#define TBLSZ (1u << 19)
#define HMASK (TBLSZ - 1u)

struct LvlParams {
    float    scale[NLVL];
    int      res[NLVL];
    unsigned densemask;
};

__global__ void __launch_bounds__(256)
nerf_field_kernel(const float* __restrict__ points,
                  const float* __restrict__ table,
                  const float* __restrict__ dw1,
                  const float* __restrict__ dw2,
                  const float* __restrict__ fw1,
                  const float* __restrict__ fw2,
                  float* __restrict__ out,
                  int N, LvlParams P)
{
    // Weights staged in shared, layer-1 transposed to [j][i] so the inner
    // i-loop reads contiguous float4 (LDS.128, uniform-address broadcast).
    __shared__ __align__(16) float s_dw1[64 * 32];
    __shared__ __align__(16) float s_fw1[64 * 32];
    __shared__ float s_dw2[64];
    __shared__ float s_fw2[64 * 3];

    for (int t = threadIdx.x; t < 2048; t += 256) {
        int i = t & 31, j = t >> 5;
        s_dw1[t] = dw1[i * 64 + j];
        s_fw1[t] = fw1[i * 64 + j];
    }
    if (threadIdx.x < 64)  s_dw2[threadIdx.x] = dw2[threadIdx.x];
    if (threadIdx.x < 192) s_fw2[threadIdx.x] = fw2[threadIdx.x];
    __syncthreads();

    int gid = blockIdx.x * 256 + threadIdx.x;
    if (gid >= N) return;

    // contract_to_unisphere: [-1,1]^3 -> [0,1]^3, clamped
    float x = fminf(fmaxf((points[gid * 3 + 0] + 1.0f) * 0.5f, 0.0f), 1.0f);
    float y = fminf(fmaxf((points[gid * 3 + 1] + 1.0f) * 0.5f, 0.0f), 1.0f);
    float z = fminf(fmaxf((points[gid * 3 + 2] + 1.0f) * 0.5f, 0.0f), 1.0f);

    float enc[32];

    #pragma unroll
    for (int l = 0; l < NLVL; l++) {
        const float sc = P.scale[l];
        const int   R  = P.res[l];
        const bool  dense = (P.densemask >> l) & 1u;

        float px = x * sc + 0.5f;
        float py = y * sc + 0.5f;
        float pz = z * sc + 0.5f;
        float fx = floorf(px), fy = floorf(py), fz = floorf(pz);
        float wx = px - fx,    wy = py - fy,    wz = pz - fz;
        int ix = (int)fx, iy = (int)fy, iz = (int)fz;

        int x0 = min(max(ix,     0), R - 1), x1 = min(max(ix + 1, 0), R - 1);
        int y0 = min(max(iy,     0), R - 1), y1 = min(max(iy + 1, 0), R - 1);
        int z0 = min(max(iz,     0), R - 1), z1 = min(max(iz + 1, 0), R - 1);

        unsigned hx[2], hy[2], hz[2];
        if (dense) {
            hx[0] = (unsigned)x0;            hx[1] = (unsigned)x1;
            hy[0] = (unsigned)(y0 * R);      hy[1] = (unsigned)(y1 * R);
            hz[0] = (unsigned)(z0 * R * R);  hz[1] = (unsigned)(z1 * R * R);
        } else {
            hx[0] = (unsigned)x0;                    hx[1] = (unsigned)x1;
            hy[0] = (unsigned)y0 * 2654435761u;      hy[1] = (unsigned)y1 * 2654435761u;
            hz[0] = (unsigned)z0 * 805459861u;       hz[1] = (unsigned)z1 * 805459861u;
        }

        unsigned idx[8];
        #pragma unroll
        for (int c = 0; c < 8; c++) {
            unsigned a = hx[(c >> 2) & 1], b = hy[(c >> 1) & 1], d = hz[c & 1];
            idx[c] = dense ? (a + b + d) : ((a ^ b ^ d) & HMASK);
        }

        const float2* tl = reinterpret_cast<const float2*>(table) + (size_t)l * TBLSZ;
        float2 g[8];
        #pragma unroll
        for (int c = 0; c < 8; c++) g[c] = __ldg(tl + idx[c]);

        float wwx[2] = {1.0f - wx, wx};
        float wwy[2] = {1.0f - wy, wy};
        float wwz[2] = {1.0f - wz, wz};
        float f0 = 0.0f, f1 = 0.0f;
        #pragma unroll
        for (int c = 0; c < 8; c++) {
            float w = wwx[(c >> 2) & 1] * wwy[(c >> 1) & 1] * wwz[c & 1];
            f0 = fmaf(w, g[c].x, f0);
            f1 = fmaf(w, g[c].y, f1);
        }
        enc[2 * l + 0] = f0;
        enc[2 * l + 1] = f1;
    }

    // Two 2-layer bias-free MLPs, streamed one hidden unit at a time:
    // keeps only enc[32] + 4 accumulators live (no 64-wide hidden vector).
    float dacc = 0.0f, c0 = 0.0f, c1 = 0.0f, c2 = 0.0f;
    #pragma unroll 2
    for (int j = 0; j < 64; j++) {
        const float4* wrow = reinterpret_cast<const float4*>(&s_dw1[j * 32]);
        const float4* frow = reinterpret_cast<const float4*>(&s_fw1[j * 32]);
        float s = 0.0f, t = 0.0f;
        #pragma unroll
        for (int i4 = 0; i4 < 8; i4++) {
            float4 wv = wrow[i4];
            float4 fv = frow[i4];
            s = fmaf(enc[i4 * 4 + 0], wv.x, s);
            s = fmaf(enc[i4 * 4 + 1], wv.y, s);
            s = fmaf(enc[i4 * 4 + 2], wv.z, s);
            s = fmaf(enc[i4 * 4 + 3], wv.w, s);
            t = fmaf(enc[i4 * 4 + 0], fv.x, t);
            t = fmaf(enc[i4 * 4 + 1], fv.y, t);
            t = fmaf(enc[i4 * 4 + 2], fv.z, t);
            t = fmaf(enc[i4 * 4 + 3], fv.w, t);
        }
        s = fmaxf(s, 0.0f);
        t = fmaxf(t, 0.0f);
        dacc = fmaf(s, s_dw2[j], dacc);
        c0 = fmaf(t, s_fw2[j * 3 + 0], c0);
        c1 = fmaf(t, s_fw2[j * 3 + 1], c1);
        c2 = fmaf(t, s_fw2[j * 3 + 2], c2);
    }

    // softplus (stable): max(x,0) + log1p(exp(-|x|))
    float density = fmaxf(dacc, 0.0f) + log1pf(expf(-fabsf(dacc)));
    float r0 = 1.0f / (1.0f + expf(-c0));
    float r1 = 1.0f / (1.0f + expf(-c1));
    float r2 = 1.0f / (1.0f + expf(-c2));

    // Output: color [N,3] then density [N,1] (tuple flatten order)
    out[gid * 3 + 0] = r0;
    out[gid * 3 + 1] = r1;
    out[gid * 3 + 2] = r2;
    out[(size_t)3 * N + gid] = density;
}

extern "C" void kernel_launch(void* const* d_in, const int* in_sizes, int n_in,
                              void* d_out, int out_size)
{
    const float* points = (const float*)d_in[0];
    const float* table  = (const float*)d_in[1];
    const float* dw1    = (const float*)d_in[2];
    const float* dw2    = (const float*)d_in[3];
    const float* fw1    = (const float*)d_in[4];
    const float* fw2    = (const float*)d_in[5];
    int N = in_sizes[0] / 3;

    LvlParams P;
    P.densemask = 0u;
    for (int l = 0; l < NLVL; l++) {
        double sc = 16.0 * pow(1.447269237440378, (double)l) - 1.0;
        int res = (int)ceil(sc) + 1;
        P.scale[l] = (float)sc;
        P.res[l] = res;
        long long r3 = (long long)res * res * res;
        if (r3 <= (long long)TBLSZ) P.densemask |= (1u << l);
    }

    int blocks = (N + 255) / 256;
    nerf_field_kernel<<<blocks, 256>>>(points, table, dw1, dw2, fw1, fw2,
                                       (float*)d_out, N, P);
}

// round 2
// speedup vs baseline: 1.0254x; 1.0254x over previous
#include <cuda_runtime.h>
#include <math.h>

#define NLVL 16
#define TBLSZ (1u << 19)
#define HMASK (TBLSZ - 1u)

struct LvlParams {
    float    scale[NLVL];
    int      res[NLVL];
    unsigned densemask;
};

__global__ void __launch_bounds__(256)
nerf_field_kernel(const float* __restrict__ points,
                  const float* __restrict__ table,
                  const float* __restrict__ dw1,
                  const float* __restrict__ dw2,
                  const float* __restrict__ fw1,
                  const float* __restrict__ fw2,
                  float* __restrict__ out,
                  int N, LvlParams P)
{
    // Layer-1 weights transposed to [j][i] in shared: inner i-loop reads
    // contiguous float4 with uniform address (conflict-free broadcast).
    __shared__ __align__(16) float s_dw1[64 * 32];
    __shared__ __align__(16) float s_fw1[64 * 32];
    __shared__ float s_dw2[64];
    __shared__ float s_fw2[64 * 3];

    for (int t = threadIdx.x; t < 2048; t += 256) {
        int i = t & 31, j = t >> 5;
        s_dw1[t] = dw1[i * 64 + j];
        s_fw1[t] = fw1[i * 64 + j];
    }
    if (threadIdx.x < 64)  s_dw2[threadIdx.x] = dw2[threadIdx.x];
    if (threadIdx.x < 192) s_fw2[threadIdx.x] = fw2[threadIdx.x];
    __syncthreads();

    int gid = blockIdx.x * 256 + threadIdx.x;
    if (gid >= N) return;

    float x = fminf(fmaxf((points[gid * 3 + 0] + 1.0f) * 0.5f, 0.0f), 1.0f);
    float y = fminf(fmaxf((points[gid * 3 + 1] + 1.0f) * 0.5f, 0.0f), 1.0f);
    float z = fminf(fmaxf((points[gid * 3 + 2] + 1.0f) * 0.5f, 0.0f), 1.0f);

    float enc[32];

    #pragma unroll
    for (int l = 0; l < NLVL; l++) {
        const float sc = P.scale[l];
        const int   R  = P.res[l];
        const bool  dense = (P.densemask >> l) & 1u;

        float px = x * sc + 0.5f;
        float py = y * sc + 0.5f;
        float pz = z * sc + 0.5f;
        float fx = floorf(px), fy = floorf(py), fz = floorf(pz);
        float wx = px - fx,    wy = py - fy,    wz = pz - fz;
        int ix = (int)fx, iy = (int)fy, iz = (int)fz;

        unsigned x0 = (unsigned)min(max(ix,     0), R - 1);
        unsigned x1 = (unsigned)min(max(ix + 1, 0), R - 1);
        int y0 = min(max(iy,     0), R - 1), y1 = min(max(iy + 1, 0), R - 1);
        int z0 = min(max(iz,     0), R - 1), z1 = min(max(iz + 1, 0), R - 1);

        // y/z hash (or stride) parts; x uses prime 1 so x-adjacent entries
        // are index-adjacent -> pairable into one aligned 16B block.
        unsigned hy[2], hz[2];
        if (dense) {
            hy[0] = (unsigned)(y0 * R);      hy[1] = (unsigned)(y1 * R);
            hz[0] = (unsigned)(z0 * R * R);  hz[1] = (unsigned)(z1 * R * R);
        } else {
            hy[0] = (unsigned)y0 * 2654435761u;  hy[1] = (unsigned)y1 * 2654435761u;
            hz[0] = (unsigned)z0 * 805459861u;   hz[1] = (unsigned)z1 * 805459861u;
        }

        const float4* t4 = reinterpret_cast<const float4*>(table) + (size_t)l * (TBLSZ / 2);

        float wwy[2] = {1.0f - wy, wy};
        float wwz[2] = {1.0f - wz, wz};
        float wA = 1.0f - wx, wB = wx;
        float f0 = 0.0f, f1 = 0.0f;

        #pragma unroll
        for (int yi = 0; yi < 2; yi++) {
            #pragma unroll
            for (int zi = 0; zi < 2; zi++) {
                unsigned h, iA, iB;
                if (dense) {
                    h  = hy[yi] + hz[zi];
                    iA = h + x0;
                    iB = h + x1;
                } else {
                    h  = hy[yi] ^ hz[zi];
                    iA = (h ^ x0) & HMASK;
                    iB = (h ^ x1) & HMASK;
                }
                unsigned pA = iA >> 1, pB = iB >> 1;
                float4 qA = __ldg(t4 + pA);
                float4 qB = qA;
                if (pB != pA) qB = __ldg(t4 + pB);   // predicated: ~50% of lanes
                float gA0 = (iA & 1) ? qA.z : qA.x;
                float gA1 = (iA & 1) ? qA.w : qA.y;
                float gB0 = (iB & 1) ? qB.z : qB.x;
                float gB1 = (iB & 1) ? qB.w : qB.y;

                float wyz = wwy[yi] * wwz[zi];
                f0 = fmaf(wyz * wA, gA0, f0);
                f1 = fmaf(wyz * wA, gA1, f1);
                f0 = fmaf(wyz * wB, gB0, f0);
                f1 = fmaf(wyz * wB, gB1, f1);
            }
        }
        enc[2 * l + 0] = f0;
        enc[2 * l + 1] = f1;
    }

    // Two 2-layer bias-free MLPs, streamed one hidden unit at a time.
    float dacc = 0.0f, c0 = 0.0f, c1 = 0.0f, c2 = 0.0f;
    #pragma unroll 2
    for (int j = 0; j < 64; j++) {
        const float4* wrow = reinterpret_cast<const float4*>(&s_dw1[j * 32]);
        const float4* frow = reinterpret_cast<const float4*>(&s_fw1[j * 32]);
        float s = 0.0f, t = 0.0f;
        #pragma unroll
        for (int i4 = 0; i4 < 8; i4++) {
            float4 wv = wrow[i4];
            float4 fv = frow[i4];
            s = fmaf(enc[i4 * 4 + 0], wv.x, s);
            s = fmaf(enc[i4 * 4 + 1], wv.y, s);
            s = fmaf(enc[i4 * 4 + 2], wv.z, s);
            s = fmaf(enc[i4 * 4 + 3], wv.w, s);
            t = fmaf(enc[i4 * 4 + 0], fv.x, t);
            t = fmaf(enc[i4 * 4 + 1], fv.y, t);
            t = fmaf(enc[i4 * 4 + 2], fv.z, t);
            t = fmaf(enc[i4 * 4 + 3], fv.w, t);
        }
        s = fmaxf(s, 0.0f);
        t = fmaxf(t, 0.0f);
        dacc = fmaf(s, s_dw2[j], dacc);
        c0 = fmaf(t, s_fw2[j * 3 + 0], c0);
        c1 = fmaf(t, s_fw2[j * 3 + 1], c1);
        c2 = fmaf(t, s_fw2[j * 3 + 2], c2);
    }

    float density = fmaxf(dacc, 0.0f) + log1pf(expf(-fabsf(dacc)));
    float r0 = 1.0f / (1.0f + expf(-c0));
    float r1 = 1.0f / (1.0f + expf(-c1));
    float r2 = 1.0f / (1.0f + expf(-c2));

    out[gid * 3 + 0] = r0;
    out[gid * 3 + 1] = r1;
    out[gid * 3 + 2] = r2;
    out[(size_t)3 * N + gid] = density;
}

extern "C" void kernel_launch(void* const* d_in, const int* in_sizes, int n_in,
                              void* d_out, int out_size)
{
    const float* points = (const float*)d_in[0];
    const float* table  = (const float*)d_in[1];
    const float* dw1    = (const float*)d_in[2];
    const float* dw2    = (const float*)d_in[3];
    const float* fw1    = (const float*)d_in[4];
    const float* fw2    = (const float*)d_in[5];
    int N = in_sizes[0] / 3;

    LvlParams P;
    P.densemask = 0u;
    for (int l = 0; l < NLVL; l++) {
        double sc = 16.0 * pow(1.447269237440378, (double)l) - 1.0;
        int res = (int)ceil(sc) + 1;
        P.scale[l] = (float)sc;
        P.res[l] = res;
        long long r3 = (long long)res * res * res;
        if (r3 <= (long long)TBLSZ) P.densemask |= (1u << l);
    }

    int blocks = (N + 255) / 256;
    nerf_field_kernel<<<blocks, 256>>>(points, table, dw1, dw2, fw1, fw2,
                                       (float*)d_out, N, P);
}

// round 3
// speedup vs baseline: 1.5195x; 1.4819x over previous
#include <cuda_runtime.h>
#include <math.h>

#define NLVL 16
#define TBLSZ (1u << 19)
#define HMASK (TBLSZ - 1u)

struct LvlParams {
    float    scale[NLVL];
    int      res[NLVL];
    unsigned densemask;
};

// Layer-1 weights transposed to [j][i] (j = hidden unit, i = input), so the
// inner i-loop reads contiguous float4 from the CONSTANT port (uniform path)
// — completely off the l1tex pipe that the gathers saturate.
__constant__ __align__(16) float c_dw1t[64 * 32];
__constant__ __align__(16) float c_fw1t[64 * 32];
__constant__ float c_dw2[64];
__constant__ float c_fw2[64 * 3];

// Scratch for the transposed weights (written by prologue kernel, then
// memcpy'd into __constant__). Static __device__ array: no allocation.
__device__ __align__(16) float g_w1t[2 * 64 * 32];

__global__ void transpose_w1_kernel(const float* __restrict__ dw1,
                                    const float* __restrict__ fw1)
{
    int t = blockIdx.x * 256 + threadIdx.x;   // 0..2047
    if (t < 2048) {
        int i = t & 31, j = t >> 5;           // t = j*32 + i
        g_w1t[t]        = dw1[i * 64 + j];
        g_w1t[2048 + t] = fw1[i * 64 + j];
    }
}

__global__ void __launch_bounds__(256)
nerf_field_kernel(const float* __restrict__ points,
                  const float* __restrict__ table,
                  float* __restrict__ out,
                  int N, LvlParams P)
{
    int gid = blockIdx.x * 256 + threadIdx.x;
    if (gid >= N) return;

    float x = fminf(fmaxf((points[gid * 3 + 0] + 1.0f) * 0.5f, 0.0f), 1.0f);
    float y = fminf(fmaxf((points[gid * 3 + 1] + 1.0f) * 0.5f, 0.0f), 1.0f);
    float z = fminf(fmaxf((points[gid * 3 + 2] + 1.0f) * 0.5f, 0.0f), 1.0f);

    float enc[32];

    #pragma unroll
    for (int l = 0; l < NLVL; l++) {
        const float sc = P.scale[l];
        const int   R  = P.res[l];
        const bool  dense = (P.densemask >> l) & 1u;

        float px = x * sc + 0.5f;
        float py = y * sc + 0.5f;
        float pz = z * sc + 0.5f;
        float fx = floorf(px), fy = floorf(py), fz = floorf(pz);
        float wx = px - fx,    wy = py - fy,    wz = pz - fz;
        int ix = (int)fx, iy = (int)fy, iz = (int)fz;

        unsigned x0 = (unsigned)min(max(ix,     0), R - 1);
        unsigned x1 = (unsigned)min(max(ix + 1, 0), R - 1);
        int y0 = min(max(iy,     0), R - 1), y1 = min(max(iy + 1, 0), R - 1);
        int z0 = min(max(iz,     0), R - 1), z1 = min(max(iz + 1, 0), R - 1);

        // x uses prime 1: x-adjacent entries are index-adjacent -> pairable
        // into one aligned 16B block (second load predicated, ~50% of lanes).
        unsigned hy[2], hz[2];
        if (dense) {
            hy[0] = (unsigned)(y0 * R);      hy[1] = (unsigned)(y1 * R);
            hz[0] = (unsigned)(z0 * R * R);  hz[1] = (unsigned)(z1 * R * R);
        } else {
            hy[0] = (unsigned)y0 * 2654435761u;  hy[1] = (unsigned)y1 * 2654435761u;
            hz[0] = (unsigned)z0 * 805459861u;   hz[1] = (unsigned)z1 * 805459861u;
        }

        const float4* t4 = reinterpret_cast<const float4*>(table) + (size_t)l * (TBLSZ / 2);

        float wwy[2] = {1.0f - wy, wy};
        float wwz[2] = {1.0f - wz, wz};
        float wA = 1.0f - wx, wB = wx;
        float f0 = 0.0f, f1 = 0.0f;

        #pragma unroll
        for (int yi = 0; yi < 2; yi++) {
            #pragma unroll
            for (int zi = 0; zi < 2; zi++) {
                unsigned h, iA, iB;
                if (dense) {
                    h  = hy[yi] + hz[zi];
                    iA = h + x0;
                    iB = h + x1;
                } else {
                    h  = hy[yi] ^ hz[zi];
                    iA = (h ^ x0) & HMASK;
                    iB = (h ^ x1) & HMASK;
                }
                unsigned pA = iA >> 1, pB = iB >> 1;
                float4 qA = __ldg(t4 + pA);
                float4 qB = qA;
                if (pB != pA) qB = __ldg(t4 + pB);   // predicated extra load
                float gA0 = (iA & 1) ? qA.z : qA.x;
                float gA1 = (iA & 1) ? qA.w : qA.y;
                float gB0 = (iB & 1) ? qB.z : qB.x;
                float gB1 = (iB & 1) ? qB.w : qB.y;

                float wyz = wwy[yi] * wwz[zi];
                f0 = fmaf(wyz * wA, gA0, f0);
                f1 = fmaf(wyz * wA, gA1, f1);
                f0 = fmaf(wyz * wB, gB0, f0);
                f1 = fmaf(wyz * wB, gB1, f1);
            }
        }
        enc[2 * l + 0] = f0;
        enc[2 * l + 1] = f1;
    }

    // Two 2-layer bias-free MLPs, one hidden unit at a time; all weight reads
    // go through the constant port (uniform across the warp), not l1tex.
    const float4* wd = reinterpret_cast<const float4*>(c_dw1t);
    const float4* wf = reinterpret_cast<const float4*>(c_fw1t);

    float dacc = 0.0f, c0 = 0.0f, c1 = 0.0f, c2 = 0.0f;
    #pragma unroll 4
    for (int j = 0; j < 64; j++) {
        float s = 0.0f, t = 0.0f;
        #pragma unroll
        for (int i4 = 0; i4 < 8; i4++) {
            float4 wv = wd[j * 8 + i4];
            float4 fv = wf[j * 8 + i4];
            s = fmaf(enc[i4 * 4 + 0], wv.x, s);
            s = fmaf(enc[i4 * 4 + 1], wv.y, s);
            s = fmaf(enc[i4 * 4 + 2], wv.z, s);
            s = fmaf(enc[i4 * 4 + 3], wv.w, s);
            t = fmaf(enc[i4 * 4 + 0], fv.x, t);
            t = fmaf(enc[i4 * 4 + 1], fv.y, t);
            t = fmaf(enc[i4 * 4 + 2], fv.z, t);
            t = fmaf(enc[i4 * 4 + 3], fv.w, t);
        }
        s = fmaxf(s, 0.0f);
        t = fmaxf(t, 0.0f);
        dacc = fmaf(s, c_dw2[j], dacc);
        c0 = fmaf(t, c_fw2[j * 3 + 0], c0);
        c1 = fmaf(t, c_fw2[j * 3 + 1], c1);
        c2 = fmaf(t, c_fw2[j * 3 + 2], c2);
    }

    float density = fmaxf(dacc, 0.0f) + log1pf(expf(-fabsf(dacc)));
    float r0 = 1.0f / (1.0f + expf(-c0));
    float r1 = 1.0f / (1.0f + expf(-c1));
    float r2 = 1.0f / (1.0f + expf(-c2));

    out[gid * 3 + 0] = r0;
    out[gid * 3 + 1] = r1;
    out[gid * 3 + 2] = r2;
    out[(size_t)3 * N + gid] = density;
}

extern "C" void kernel_launch(void* const* d_in, const int* in_sizes, int n_in,
                              void* d_out, int out_size)
{
    const float* points = (const float*)d_in[0];
    const float* table  = (const float*)d_in[1];
    const float* dw1    = (const float*)d_in[2];
    const float* dw2    = (const float*)d_in[3];
    const float* fw1    = (const float*)d_in[4];
    const float* fw2    = (const float*)d_in[5];
    int N = in_sizes[0] / 3;

    // Stage weights: transpose layer-1 into __device__ scratch, then D2D
    // copies into __constant__ (all graph-capturable: kernels + async D2D).
    transpose_w1_kernel<<<8, 256>>>(dw1, fw1);
    void* src = nullptr;
    cudaGetSymbolAddress(&src, g_w1t);
    cudaMemcpyToSymbolAsync(c_dw1t, src, 2048 * sizeof(float), 0,
                            cudaMemcpyDeviceToDevice, 0);
    cudaMemcpyToSymbolAsync(c_fw1t, (const char*)src + 2048 * sizeof(float),
                            2048 * sizeof(float), 0,
                            cudaMemcpyDeviceToDevice, 0);
    cudaMemcpyToSymbolAsync(c_dw2, dw2, 64 * sizeof(float), 0,
                            cudaMemcpyDeviceToDevice, 0);
    cudaMemcpyToSymbolAsync(c_fw2, fw2, 192 * sizeof(float), 0,
                            cudaMemcpyDeviceToDevice, 0);

    LvlParams P;
    P.densemask = 0u;
    for (int l = 0; l < NLVL; l++) {
        double sc = 16.0 * pow(1.447269237440378, (double)l) - 1.0;
        int res = (int)ceil(sc) + 1;
        P.scale[l] = (float)sc;
        P.res[l] = res;
        long long r3 = (long long)res * res * res;
        if (r3 <= (long long)TBLSZ) P.densemask |= (1u << l);
    }

    int blocks = (N + 255) / 256;
    nerf_field_kernel<<<blocks, 256>>>(points, table, (float*)d_out, N, P);
}

// round 4
// speedup vs baseline: 1.7401x; 1.1451x over previous
#include <cuda_runtime.h>
#include <math.h>

#define NLVL 16
#define TBLSZ (1u << 19)
#define HMASK (TBLSZ - 1u)

typedef unsigned long long ull;

struct LvlParams {
    float    scale[NLVL];
    int      res[NLVL];
    unsigned densemask;
};

// Layer-1 weights transposed to [j][i]; pairs (i, i+1) contiguous so they load
// as b64 from the constant port and feed fma.rn.f32x2 directly.
__constant__ __align__(16) float c_dw1t[64 * 32];
__constant__ __align__(16) float c_fw1t[64 * 32];
// Layer-2 weights pre-interleaved as pairs: w2a[j] = (dw2[j], fw2[j][0]),
// w2b[j] = (fw2[j][1], fw2[j][2]).
__constant__ __align__(16) float c_w2a[128];
__constant__ __align__(16) float c_w2b[128];

// Scratch written by prologue kernel, then D2D-copied into __constant__.
__device__ __align__(16) float g_wscratch[4352];

__global__ void prep_weights_kernel(const float* __restrict__ dw1,
                                    const float* __restrict__ fw1,
                                    const float* __restrict__ dw2,
                                    const float* __restrict__ fw2)
{
    int t = blockIdx.x * 256 + threadIdx.x;   // 0..2047
    if (t < 2048) {
        int i = t & 31, j = t >> 5;           // t = j*32 + i
        g_wscratch[t]        = dw1[i * 64 + j];
        g_wscratch[2048 + t] = fw1[i * 64 + j];
    }
    if (t < 64) {
        g_wscratch[4096 + 2 * t + 0] = dw2[t];
        g_wscratch[4096 + 2 * t + 1] = fw2[3 * t + 0];
        g_wscratch[4224 + 2 * t + 0] = fw2[3 * t + 1];
        g_wscratch[4224 + 2 * t + 1] = fw2[3 * t + 2];
    }
}

__device__ __forceinline__ ull pack2(float lo, float hi) {
    ull r;
    asm("mov.b64 %0, {%1, %2};" : "=l"(r) : "f"(lo), "f"(hi));
    return r;
}
__device__ __forceinline__ float2 unpack2(ull v) {
    float2 r;
    asm("mov.b64 {%0, %1}, %2;" : "=f"(r.x), "=f"(r.y) : "l"(v));
    return r;
}
__device__ __forceinline__ ull fma2(ull a, ull b, ull c) {
    ull d;
    asm("fma.rn.f32x2 %0, %1, %2, %3;" : "=l"(d) : "l"(a), "l"(b), "l"(c));
    return d;
}

__global__ void __launch_bounds__(256)
nerf_field_kernel(const float* __restrict__ points,
                  const float* __restrict__ table,
                  float* __restrict__ out,
                  int N, LvlParams P)
{
    int gid = blockIdx.x * 256 + threadIdx.x;
    if (gid >= N) return;

    float x = fminf(fmaxf((points[gid * 3 + 0] + 1.0f) * 0.5f, 0.0f), 1.0f);
    float y = fminf(fmaxf((points[gid * 3 + 1] + 1.0f) * 0.5f, 0.0f), 1.0f);
    float z = fminf(fmaxf((points[gid * 3 + 2] + 1.0f) * 0.5f, 0.0f), 1.0f);

    ull encp[16];   // enc as 16 packed float pairs (one per level)

    #pragma unroll
    for (int l = 0; l < NLVL; l++) {
        const float sc = P.scale[l];
        const int   R  = P.res[l];
        const bool  dense = (P.densemask >> l) & 1u;

        float px = x * sc + 0.5f;
        float py = y * sc + 0.5f;
        float pz = z * sc + 0.5f;
        float fx = floorf(px), fy = floorf(py), fz = floorf(pz);
        float wx = px - fx,    wy = py - fy,    wz = pz - fz;
        int ix = (int)fx, iy = (int)fy, iz = (int)fz;

        unsigned x0 = (unsigned)min(max(ix,     0), R - 1);
        unsigned x1 = (unsigned)min(max(ix + 1, 0), R - 1);
        int y0 = min(max(iy,     0), R - 1), y1 = min(max(iy + 1, 0), R - 1);
        int z0 = min(max(iz,     0), R - 1), z1 = min(max(iz + 1, 0), R - 1);

        // x uses prime 1: x-adjacent entries are index-adjacent -> pairable
        // into one aligned 16B block (second load predicated, ~50% of lanes).
        unsigned hy[2], hz[2];
        if (dense) {
            hy[0] = (unsigned)(y0 * R);      hy[1] = (unsigned)(y1 * R);
            hz[0] = (unsigned)(z0 * R * R);  hz[1] = (unsigned)(z1 * R * R);
        } else {
            hy[0] = (unsigned)y0 * 2654435761u;  hy[1] = (unsigned)y1 * 2654435761u;
            hz[0] = (unsigned)z0 * 805459861u;   hz[1] = (unsigned)z1 * 805459861u;
        }

        const float4* t4 = reinterpret_cast<const float4*>(table) + (size_t)l * (TBLSZ / 2);

        float wwy[2] = {1.0f - wy, wy};
        float wwz[2] = {1.0f - wz, wz};
        float wA = 1.0f - wx, wB = wx;
        ull f01 = 0ull;   // packed (feat0, feat1) accumulator

        #pragma unroll
        for (int yi = 0; yi < 2; yi++) {
            #pragma unroll
            for (int zi = 0; zi < 2; zi++) {
                unsigned h, iA, iB;
                if (dense) {
                    h  = hy[yi] + hz[zi];
                    iA = h + x0;
                    iB = h + x1;
                } else {
                    h  = hy[yi] ^ hz[zi];
                    iA = (h ^ x0) & HMASK;
                    iB = (h ^ x1) & HMASK;
                }
                unsigned pA = iA >> 1, pB = iB >> 1;
                float4 qA = __ldg(t4 + pA);
                float4 qB = qA;
                if (pB != pA) qB = __ldg(t4 + pB);   // predicated extra load

                // Feature pair = one 64-bit half of the 16B block.
                ull gA = (iA & 1) ? pack2(qA.z, qA.w) : pack2(qA.x, qA.y);
                ull gB = (iB & 1) ? pack2(qB.z, qB.w) : pack2(qB.x, qB.y);

                float wyz = wwy[yi] * wwz[zi];
                float wAyz = wyz * wA, wByz = wyz * wB;
                f01 = fma2(pack2(wAyz, wAyz), gA, f01);
                f01 = fma2(pack2(wByz, wByz), gB, f01);
            }
        }
        encp[l] = f01;
    }

    // Two 2-layer bias-free MLPs with packed-pair FMAs.
    const ull* wd  = reinterpret_cast<const ull*>(c_dw1t);   // [64][16]
    const ull* wf  = reinterpret_cast<const ull*>(c_fw1t);
    const ull* w2a = reinterpret_cast<const ull*>(c_w2a);    // [64]
    const ull* w2b = reinterpret_cast<const ull*>(c_w2b);

    ull dc = 0ull;   // (density_acc, color0)
    ull cc = 0ull;   // (color1, color2)
    #pragma unroll 4
    for (int j = 0; j < 64; j++) {
        ull s2 = 0ull, t2 = 0ull;
        #pragma unroll
        for (int k = 0; k < 16; k++) {
            s2 = fma2(encp[k], wd[j * 16 + k], s2);
            t2 = fma2(encp[k], wf[j * 16 + k], t2);
        }
        float2 sv = unpack2(s2), tv = unpack2(t2);
        float s = fmaxf(sv.x + sv.y, 0.0f);
        float t = fmaxf(tv.x + tv.y, 0.0f);
        dc = fma2(pack2(s, t), w2a[j], dc);
        cc = fma2(pack2(t, t), w2b[j], cc);
    }

    float2 dcv = unpack2(dc);
    float2 ccv = unpack2(cc);
    float dacc = dcv.x, c0 = dcv.y, c1 = ccv.x, c2 = ccv.y;

    float density = fmaxf(dacc, 0.0f) + log1pf(expf(-fabsf(dacc)));
    float r0 = 1.0f / (1.0f + expf(-c0));
    float r1 = 1.0f / (1.0f + expf(-c1));
    float r2 = 1.0f / (1.0f + expf(-c2));

    out[gid * 3 + 0] = r0;
    out[gid * 3 + 1] = r1;
    out[gid * 3 + 2] = r2;
    out[(size_t)3 * N + gid] = density;
}

extern "C" void kernel_launch(void* const* d_in, const int* in_sizes, int n_in,
                              void* d_out, int out_size)
{
    const float* points = (const float*)d_in[0];
    const float* table  = (const float*)d_in[1];
    const float* dw1    = (const float*)d_in[2];
    const float* dw2    = (const float*)d_in[3];
    const float* fw1    = (const float*)d_in[4];
    const float* fw2    = (const float*)d_in[5];
    int N = in_sizes[0] / 3;

    // Stage weights: transpose/interleave into __device__ scratch, then D2D
    // into __constant__ (kernels + async D2D: graph-capturable, no allocs).
    prep_weights_kernel<<<8, 256>>>(dw1, fw1, dw2, fw2);
    void* src = nullptr;
    cudaGetSymbolAddress(&src, g_wscratch);
    cudaMemcpyToSymbolAsync(c_dw1t, src, 2048 * sizeof(float), 0,
                            cudaMemcpyDeviceToDevice, 0);
    cudaMemcpyToSymbolAsync(c_fw1t, (const char*)src + 2048 * sizeof(float),
                            2048 * sizeof(float), 0,
                            cudaMemcpyDeviceToDevice, 0);
    cudaMemcpyToSymbolAsync(c_w2a, (const char*)src + 4096 * sizeof(float),
                            128 * sizeof(float), 0,
                            cudaMemcpyDeviceToDevice, 0);
    cudaMemcpyToSymbolAsync(c_w2b, (const char*)src + 4224 * sizeof(float),
                            128 * sizeof(float), 0,
                            cudaMemcpyDeviceToDevice, 0);

    LvlParams P;
    P.densemask = 0u;
    for (int l = 0; l < NLVL; l++) {
        double sc = 16.0 * pow(1.447269237440378, (double)l) - 1.0;
        int res = (int)ceil(sc) + 1;
        P.scale[l] = (float)sc;
        P.res[l] = res;
        long long r3 = (long long)res * res * res;
        if (r3 <= (long long)TBLSZ) P.densemask |= (1u << l);
    }

    int blocks = (N + 255) / 256;
    nerf_field_kernel<<<blocks, 256>>>(points, table, (float*)d_out, N, P);
}